// round 7
// baseline (speedup 1.0000x reference)
#include <cuda_runtime.h>
#include <cuda_bf16.h>
#include <math.h>
#include <stdint.h>

#define BATCH 16
#define MAXPIX (268u * 268u)

// activations NHWC bf16, separate hi/lo, ping-pong pairs
__device__ __nv_bfloat16 g_ah[16u * MAXPIX * 64u];
__device__ __nv_bfloat16 g_al[16u * MAXPIX * 64u];
__device__ __nv_bfloat16 g_bh[16u * MAXPIX * 64u];
__device__ __nv_bfloat16 g_bl[16u * MAXPIX * 64u];
// pre-split body weights, K-MAJOR: [5][16][tap 9][ic 64][oc 64] bf16
__device__ __nv_bfloat16 g_wth[5u * 16u * 9u * 64u * 64u];
__device__ __nv_bfloat16 g_wtl[5u * 16u * 9u * 64u * 64u];

// ---------------- helpers ----------------
__device__ __forceinline__ uint32_t smem_u32(const void* p) {
    uint32_t a;
    asm("{ .reg .u64 t; cvta.to.shared.u64 t, %1; cvt.u32.u64 %0, t; }" : "=r"(a) : "l"(p));
    return a;
}
__device__ __forceinline__ uint32_t swz(uint32_t o) { return o ^ ((o >> 3) & 0x70); }

__device__ __forceinline__ void ldsm4(uint32_t r[4], uint32_t addr) {
    asm volatile("ldmatrix.sync.aligned.m8n8.x4.shared.b16 {%0,%1,%2,%3}, [%4];"
        : "=r"(r[0]), "=r"(r[1]), "=r"(r[2]), "=r"(r[3]) : "r"(addr));
}
__device__ __forceinline__ void ldsm4t(uint32_t r[4], uint32_t addr) {
    asm volatile("ldmatrix.sync.aligned.m8n8.x4.trans.shared.b16 {%0,%1,%2,%3}, [%4];"
        : "=r"(r[0]), "=r"(r[1]), "=r"(r[2]), "=r"(r[3]) : "r"(addr));
}
__device__ __forceinline__ void mma16816(float d[4], const uint32_t a[4], uint32_t b0, uint32_t b1) {
    asm volatile("mma.sync.aligned.m16n8k16.row.col.f32.bf16.bf16.f32 "
        "{%0,%1,%2,%3}, {%4,%5,%6,%7}, {%8,%9}, {%0,%1,%2,%3};"
        : "+f"(d[0]), "+f"(d[1]), "+f"(d[2]), "+f"(d[3])
        : "r"(a[0]), "r"(a[1]), "r"(a[2]), "r"(a[3]), "r"(b0), "r"(b1));
}
__device__ __forceinline__ void cp16(uint32_t dst, const void* src) {
    asm volatile("cp.async.cg.shared.global [%0], [%1], 16;" :: "r"(dst), "l"(src) : "memory");
}
#define CP_COMMIT() asm volatile("cp.async.commit_group;" ::: "memory")
#define CP_WAIT(n)  asm volatile("cp.async.wait_group %0;" :: "n"(n) : "memory")

// smem layout for body kernel
#define SM_WS   0          // 18 x 8192 = 147456
#define SM_HI0  147456
#define SM_HI1  171008
#define SM_LO   194560
#define SMEM_BODY 218112

#define NTHR 512

// ---------------- weight prep: [l][b][tap][ic][oc], cw folded, bf16 split ----
__global__ void prep_kernel(const float* __restrict__ bw, float cw) {
    int idx = blockIdx.x * blockDim.x + threadIdx.x;
    const int N = 5 * 16 * 9 * 64 * 64;
    if (idx >= N) return;
    int oc = idx & 63;
    int ic = (idx >> 6) & 63;
    int tap = (idx >> 12) % 9;
    int rest = idx / (9 * 64 * 64);   // l*16+b
    float v = bw[(((size_t)rest * 64 + oc) * 64 + ic) * 9 + tap] * cw;
    __nv_bfloat16 h = __float2bfloat16(v);
    __nv_bfloat16 l = __float2bfloat16(v - __bfloat162float(h));
    g_wth[idx] = h;
    g_wtl[idx] = l;
}

// ---------------- head (scalar fp32, writes NHWC hi/lo) ----------------
__global__ __launch_bounds__(256)
void head_kernel(const float* __restrict__ noise, const float* __restrict__ hw,
                 const float* __restrict__ hb, __nv_bfloat16* __restrict__ oh,
                 __nv_bfloat16* __restrict__ ol, float cw, float cb)
{
    const int Sout = 268;
    int b = blockIdx.z >> 2;
    int oc0 = (blockIdx.z & 3) << 4;
    int tx0 = blockIdx.x * 32, ty0 = blockIdx.y * 8;
    int tid = threadIdx.x, tx = tid & 31, ty = tid >> 5;

    __shared__ __align__(16) float ws[3 * 9 * 16];
    __shared__ float xs[3 * 10 * 34];

    for (int i = tid; i < 3 * 144; i += 256) {
        int oc = i & 15, k = (i >> 4) % 9, ic = i / 144;
        ws[i] = hw[((b * 64 + oc0 + oc) * 3 + ic) * 9 + k];
    }
    for (int i = tid; i < 3 * 340; i += 256) {
        int ic = i / 340, rem = i % 340, r = rem / 34, c = rem % 34;
        int gy = ty0 + r - 7, gx = tx0 + c - 7;
        float v = 0.f;
        if (gy >= 0 && gy < 256 && gx >= 0 && gx < 256)
            v = noise[((size_t)(b * 3 + ic) * 256 + gy) * 256 + gx];
        xs[i] = v;
    }
    __syncthreads();

    float acc[16];
#pragma unroll
    for (int o = 0; o < 16; o++) acc[o] = 0.f;
#pragma unroll
    for (int ic = 0; ic < 3; ic++) {
        const float* xp = xs + ic * 340 + ty * 34 + tx;
        float xv[9];
#pragma unroll
        for (int ky = 0; ky < 3; ky++)
#pragma unroll
            for (int kx = 0; kx < 3; kx++) xv[ky * 3 + kx] = xp[ky * 34 + kx];
        const float4* wp = (const float4*)(ws + ic * 144);
#pragma unroll
        for (int k = 0; k < 9; k++) {
#pragma unroll
            for (int q = 0; q < 4; q++) {
                float4 w4 = wp[k * 4 + q];
                acc[q * 4 + 0] = fmaf(xv[k], w4.x, acc[q * 4 + 0]);
                acc[q * 4 + 1] = fmaf(xv[k], w4.y, acc[q * 4 + 1]);
                acc[q * 4 + 2] = fmaf(xv[k], w4.z, acc[q * 4 + 2]);
                acc[q * 4 + 3] = fmaf(xv[k], w4.w, acc[q * 4 + 3]);
            }
        }
    }

    int ox = tx0 + tx, oy = ty0 + ty;
    if (ox < Sout && oy < Sout) {
        __align__(16) __nv_bfloat16 h16[16], l16[16];
#pragma unroll
        for (int o = 0; o < 16; o++) {
            float v = acc[o] * cw + hb[b * 64 + oc0 + o] * cb;
            v = v > 0.f ? v : 0.02f * v;
            h16[o] = __float2bfloat16(v);
            l16[o] = __float2bfloat16(v - __bfloat162float(h16[o]));
        }
        size_t obase = ((size_t)b * (Sout * Sout) + (size_t)oy * Sout + ox) * 64 + oc0;
        uint4* dh = (uint4*)(oh + obase);
        uint4* dl = (uint4*)(ol + obase);
        dh[0] = ((uint4*)h16)[0]; dh[1] = ((uint4*)h16)[1];
        dl[0] = ((uint4*)l16)[0]; dl[1] = ((uint4*)l16)[1];
    }
}

// ---------------- body A-slab gather via cp.async ----------------
__device__ __forceinline__ void gather_cp(uint32_t dst, const __nv_bfloat16* __restrict__ src,
                                          int oy0, int ox0, int Sin, int tid)
{
    // slab: 10 rows x 18 px x 64 ch bf16 -> 1440 16B chunks, SW128 swizzled
    for (int i = tid; i < 1440; i += NTHR) {
        int e = i >> 3, q = i & 7;
        int er = e / 18, ec = e - er * 18;
        int iy = oy0 + er; if (iy > Sin - 1) iy = Sin - 1;
        int ix = ox0 + ec; if (ix > Sin - 1) ix = Sin - 1;
        const void* s = src + ((size_t)iy * Sin + ix) * 64 + q * 8;
        cp16(dst + swz((uint32_t)(e * 128 + q * 16)), s);
    }
    CP_COMMIT();
}

// ---------------- body (mma.sync bf16 3-term split, 16 warps) ----------------
__global__ __launch_bounds__(NTHR, 1)
void body_mma_kernel(const __nv_bfloat16* __restrict__ in_h,
                     const __nv_bfloat16* __restrict__ in_l,
                     const __nv_bfloat16* __restrict__ wth,   // [16][9][64 ic][64 oc]
                     const __nv_bfloat16* __restrict__ wtl,
                     const float* __restrict__ bias,          // [16][64]
                     __nv_bfloat16* __restrict__ out_h,
                     __nv_bfloat16* __restrict__ out_l,
                     int Sin, float cb)
{
    extern __shared__ __align__(1024) char smem[];
    const int Sout = Sin - 2;
    const int b = blockIdx.z, slot = blockIdx.x;
    const int tid = threadIdx.x, wid = tid >> 5, lane = tid & 31;
    const int wm = wid & 3, wn = wid >> 2;       // 4 x 4 warp grid
    uint32_t sbase = smem_u32(smem);
    const uint32_t HI[2] = { sbase + SM_HI0, sbase + SM_HI1 };
    const uint32_t LO = sbase + SM_LO;

    // stage weights: [tap][half][ic 64][128B oc], SW128-swizzled
    {
        const __nv_bfloat16* whb = wth + (size_t)b * 9 * 4096;
        const __nv_bfloat16* wlb = wtl + (size_t)b * 9 * 4096;
        for (int i = tid; i < 9216; i += NTHR) {
            int j = i & 511, th = i >> 9;
            int ic = j >> 3, q = j & 7;
            int tap = th >> 1, h = th & 1;
            const uint4* src = (const uint4*)((h ? wlb : whb) + ((size_t)tap * 64 + ic) * 64) + q;
            *(uint4*)(smem + SM_WS + th * 8192 + swz(ic * 128 + q * 16)) = *src;
        }
    }

    // per-thread bias: oc = wn*16 + j*8 + (lane&3)*2, j = 0,1
    float bv[4];
#pragma unroll
    for (int j = 0; j < 2; j++) {
        int oc = wn * 16 + j * 8 + (lane & 3) * 2;
        bv[j * 2 + 0] = bias[b * 64 + oc] * cb;
        bv[j * 2 + 1] = bias[b * 64 + oc + 1] * cb;
    }

    const __nv_bfloat16* ih = in_h + (size_t)b * Sin * Sin * 64;
    const __nv_bfloat16* il = in_l + (size_t)b * Sin * Sin * 64;
    const int nrt = (Sout + 7) >> 3, nct = (Sout + 15) >> 4;
    const int ntiles = nrt * nct;
    const size_t Spo = (size_t)Sout * Sout;

    const int laneA = (lane & 15) * 128 + (lane >> 4) * 16;
    const int laneB = (lane & 15) * 128 + (lane >> 4) * 16 + wn * 32;

    int s = 0;
    // prologue: prefetch hi slab of first tile
    {
        int t0 = slot;
        if (t0 < ntiles) {
            int rt = t0 / nct, ct = t0 - rt * nct;
            gather_cp(HI[0], ih, rt * 8, ct * 16, Sin, tid);
        } else {
            CP_COMMIT();
        }
    }

    for (int tt = slot; tt < ntiles; tt += 9) {
        int rt = tt / nct, ct = tt - rt * nct;
        int oy0 = rt * 8, ox0 = ct * 16;
        int tn = (tt + 9 < ntiles) ? tt + 9 : tt;
        int rtn = tn / nct, ctn = tn - rtn * nct;

        __syncthreads();                       // (a) lo + hi[1-s] free
        gather_cp(LO, il, oy0, ox0, Sin, tid);            // group: lo(t)
        gather_cp(HI[1 - s], ih, rtn * 8, ctn * 16, Sin, tid); // group: hi(t+1)
        CP_WAIT(2); __syncthreads();           // (b) hi[s] ready

        float acc[2][2][4];
#pragma unroll
        for (int mt = 0; mt < 2; mt++)
#pragma unroll
            for (int j = 0; j < 2; j++)
#pragma unroll
                for (int r = 0; r < 4; r++) acc[mt][j][r] = 0.f;

        // phase 1: AhBh + AhBl
#pragma unroll
        for (int ky = 0; ky < 3; ky++) {
#pragma unroll
            for (int kx = 0; kx < 3; kx++) {
                uint32_t wtile = sbase + SM_WS + (ky * 3 + kx) * 16384;
#pragma unroll
                for (int kc = 0; kc < 4; kc++) {
                    uint32_t a_h[2][4];
#pragma unroll
                    for (int mt = 0; mt < 2; mt++) {
                        int ebase = ((wm * 2 + mt + ky) * 18 + kx) * 128 + kc * 32;
                        ldsm4(a_h[mt], HI[s] + swz((uint32_t)(ebase + laneA)));
                    }
                    uint32_t b_h[4], b_l[4];
                    {
                        uint32_t off = swz((uint32_t)(kc * 2048 + laneB));
                        ldsm4t(b_h, wtile + off);
                        ldsm4t(b_l, wtile + 8192 + off);
                    }
#pragma unroll
                    for (int mt = 0; mt < 2; mt++) {
#pragma unroll
                        for (int j = 0; j < 2; j++) {
                            mma16816(acc[mt][j], a_h[mt], b_h[j * 2], b_h[j * 2 + 1]);
                            mma16816(acc[mt][j], a_h[mt], b_l[j * 2], b_l[j * 2 + 1]);
                        }
                    }
                }
            }
        }

        CP_WAIT(1); __syncthreads();           // (c) lo ready

        // phase 2: AlBh
#pragma unroll
        for (int ky = 0; ky < 3; ky++) {
#pragma unroll
            for (int kx = 0; kx < 3; kx++) {
                uint32_t wtile = sbase + SM_WS + (ky * 3 + kx) * 16384;
#pragma unroll
                for (int kc = 0; kc < 4; kc++) {
                    uint32_t a_l[2][4];
#pragma unroll
                    for (int mt = 0; mt < 2; mt++) {
                        int ebase = ((wm * 2 + mt + ky) * 18 + kx) * 128 + kc * 32;
                        ldsm4(a_l[mt], LO + swz((uint32_t)(ebase + laneA)));
                    }
                    uint32_t b_h[4];
                    ldsm4t(b_h, wtile + swz((uint32_t)(kc * 2048 + laneB)));
#pragma unroll
                    for (int mt = 0; mt < 2; mt++) {
#pragma unroll
                        for (int j = 0; j < 2; j++) {
                            mma16816(acc[mt][j], a_l[mt], b_h[j * 2], b_h[j * 2 + 1]);
                        }
                    }
                }
            }
        }

        // epilogue: bias + leaky, split hi/lo, store
#pragma unroll
        for (int mt = 0; mt < 2; mt++) {
            int oy = oy0 + wm * 2 + mt;
            if (oy >= Sout) continue;
#pragma unroll
            for (int rs = 0; rs < 2; rs++) {
                int c = (lane >> 2) + rs * 8;
                int ox = ox0 + c;
                if (ox >= Sout) continue;
                size_t pix = (size_t)oy * Sout + ox;
                size_t eoff = ((size_t)b * Spo + pix) * 64 + wn * 16 + (lane & 3) * 2;
#pragma unroll
                for (int j = 0; j < 2; j++) {
                    float v0 = acc[mt][j][rs * 2 + 0] + bv[j * 2 + 0];
                    float v1 = acc[mt][j][rs * 2 + 1] + bv[j * 2 + 1];
                    v0 = v0 > 0.f ? v0 : 0.02f * v0;
                    v1 = v1 > 0.f ? v1 : 0.02f * v1;
                    __nv_bfloat16 h0 = __float2bfloat16(v0);
                    __nv_bfloat16 h1 = __float2bfloat16(v1);
                    __nv_bfloat16 l0 = __float2bfloat16(v0 - __bfloat162float(h0));
                    __nv_bfloat16 l1 = __float2bfloat16(v1 - __bfloat162float(h1));
                    unsigned ph = (unsigned)__bfloat16_as_ushort(h0) | ((unsigned)__bfloat16_as_ushort(h1) << 16);
                    unsigned pl = (unsigned)__bfloat16_as_ushort(l0) | ((unsigned)__bfloat16_as_ushort(l1) << 16);
                    *(unsigned*)(out_h + eoff + j * 8) = ph;
                    *(unsigned*)(out_l + eoff + j * 8) = pl;
                }
            }
        }
        s ^= 1;
    }
}

// ---------------- tail (scalar, reads NHWC hi/lo) ----------------
__global__ __launch_bounds__(256)
void tail_kernel(const __nv_bfloat16* __restrict__ in_h,
                 const __nv_bfloat16* __restrict__ in_l,
                 const float* __restrict__ w, const float* __restrict__ bias,
                 float* __restrict__ out, float cw, float cb)
{
    extern __shared__ float sm[];
    float* ws = sm;              // 64*27
    float* xs = sm + 1728;       // 64 ic x 340 px
    const int Sin = 258, Sout = 256;
    int b = blockIdx.z;
    int tx0 = blockIdx.x * 32, ty0 = blockIdx.y * 8;
    int tid = threadIdx.x, tx = tid & 31, ty = tid >> 5;

    for (int i = tid; i < 64 * 27; i += 256) {
        int oc = i % 3, k = (i / 3) % 9, ic = i / 27;
        ws[i] = w[((b * 3 + oc) * 64 + ic) * 9 + k];
    }
    const __nv_bfloat16* ihb = in_h + (size_t)b * Sin * Sin * 64;
    const __nv_bfloat16* ilb = in_l + (size_t)b * Sin * Sin * 64;
    for (int i = tid; i < 2720; i += 256) {
        int p = i >> 3, g = i & 7;
        int py = p / 34, px = p - py * 34;
        size_t pb = ((size_t)(ty0 + py) * Sin + tx0 + px) * 64 + g * 8;
        uint4 H = *(const uint4*)(ihb + pb);
        uint4 L = *(const uint4*)(ilb + pb);
        const unsigned* hu = (const unsigned*)&H;
        const unsigned* lu = (const unsigned*)&L;
#pragma unroll
        for (int j = 0; j < 4; j++) {
            float2 fh = __bfloat1622float2(*(const __nv_bfloat162*)&hu[j]);
            float2 fl = __bfloat1622float2(*(const __nv_bfloat162*)&lu[j]);
            xs[(g * 8 + j * 2 + 0) * 340 + p] = fh.x + fl.x;
            xs[(g * 8 + j * 2 + 1) * 340 + p] = fh.y + fl.y;
        }
    }
    __syncthreads();

    float acc[3] = {0.f, 0.f, 0.f};
#pragma unroll 4
    for (int ic = 0; ic < 64; ic++) {
        const float* xp = xs + ic * 340 + ty * 34 + tx;
        float xv[9];
#pragma unroll
        for (int ky = 0; ky < 3; ky++)
#pragma unroll
            for (int kx = 0; kx < 3; kx++) xv[ky * 3 + kx] = xp[ky * 34 + kx];
        const float* wp = ws + ic * 27;
#pragma unroll
        for (int k = 0; k < 9; k++)
#pragma unroll
            for (int o = 0; o < 3; o++) acc[o] = fmaf(xv[k], wp[k * 3 + o], acc[o]);
    }

    int ox = tx0 + tx, oy = ty0 + ty;
    size_t obase = ((size_t)(b * 3)) * 65536 + (size_t)oy * 256 + ox;
#pragma unroll
    for (int o = 0; o < 3; o++)
        out[obase + (size_t)o * 65536] = tanhf(acc[o] * cw + bias[b * 3 + o] * cb);
}

// ---------------- launch ----------------
extern "C" void kernel_launch(void* const* d_in, const int* in_sizes, int n_in,
                              void* d_out, int out_size)
{
    const float* noise  = (const float*)d_in[0];
    const float* head_w = (const float*)d_in[1];
    const float* head_b = (const float*)d_in[2];
    const float* body_w = (const float*)d_in[3];
    const float* body_b = (const float*)d_in[4];
    const float* tail_w = (const float*)d_in[5];
    const float* tail_b = (const float*)d_in[6];
    float* out = (float*)d_out;

    __nv_bfloat16 *ah, *al, *bh, *bl, *wth, *wtl;
    cudaGetSymbolAddress((void**)&ah, g_ah);
    cudaGetSymbolAddress((void**)&al, g_al);
    cudaGetSymbolAddress((void**)&bh, g_bh);
    cudaGetSymbolAddress((void**)&bl, g_bl);
    cudaGetSymbolAddress((void**)&wth, g_wth);
    cudaGetSymbolAddress((void**)&wtl, g_wtl);

    cudaFuncSetAttribute(body_mma_kernel, cudaFuncAttributeMaxDynamicSharedMemorySize, SMEM_BODY);
    cudaFuncSetAttribute(tail_kernel, cudaFuncAttributeMaxDynamicSharedMemorySize, 94208);

    const double lr_gain = sqrt(2.0 / (1.0 + 0.02 * 0.02));
    const float cw_head = (float)(lr_gain / sqrt(27.0));
    const float cb_head = (float)(1.0 / sqrt(3.0));
    const float cw_body = (float)(lr_gain / 24.0);
    const float cb_body = 0.125f;
    const float cw_tail = (float)((5.0 / 3.0) / 24.0);
    const float cb_tail = 0.125f;

    // body weight prep (fold cw, bf16 split, k-major)
    {
        int N = 5 * 16 * 9 * 64 * 64;
        prep_kernel<<<(N + 255) / 256, 256>>>(body_w, cw_body);
    }

    // head -> (ah, al) (268)
    {
        dim3 grid((268 + 31) / 32, (268 + 7) / 8, BATCH * 4);
        head_kernel<<<grid, 256>>>(noise, head_w, head_b, ah, al, cw_head, cb_head);
    }

    // 5 body layers, ping-pong hi/lo buffers
    __nv_bfloat16 *sh = ah, *sl = al, *dh = bh, *dl = bl;
    int Sin = 268;
    for (int l = 0; l < 5; l++) {
        dim3 grid(9, 1, BATCH);
        const __nv_bfloat16* wh_l = wth + (size_t)l * 16 * 9 * 4096;
        const __nv_bfloat16* wl_l = wtl + (size_t)l * 16 * 9 * 4096;
        const float* bias_l = body_b + (size_t)l * 16 * 64;
        body_mma_kernel<<<grid, NTHR, SMEM_BODY>>>(sh, sl, wh_l, wl_l, bias_l,
                                                   dh, dl, Sin, cb_body);
        __nv_bfloat16* t;
        t = sh; sh = dh; dh = t;
        t = sl; sl = dl; dl = t;
        Sin -= 2;
    }

    // tail: (sh, sl) 258 -> out 256
    {
        dim3 grid(256 / 32, 256 / 8, BATCH);
        tail_kernel<<<grid, 256, 94208>>>(sh, sl, tail_w, tail_b, out, cw_tail, cb_tail);
    }
}

// round 8
// speedup vs baseline: 1.3835x; 1.3835x over previous
#include <cuda_runtime.h>
#include <cuda_fp16.h>
#include <math.h>
#include <stdint.h>

#define BATCH 16
#define MAXPIX (268u * 268u)

// activations NHWC fp16, separate hi/lo, ping-pong pairs
__device__ __half g_ah[16u * MAXPIX * 64u];
__device__ __half g_al[16u * MAXPIX * 64u];
__device__ __half g_bh[16u * MAXPIX * 64u];
__device__ __half g_bl[16u * MAXPIX * 64u];
// fp16 body weights, K-MAJOR: [5][16][tap 9][ic 64][oc 64]
__device__ __half g_wt[5u * 16u * 9u * 64u * 64u];

// ---------------- helpers ----------------
__device__ __forceinline__ uint32_t smem_u32(const void* p) {
    uint32_t a;
    asm("{ .reg .u64 t; cvta.to.shared.u64 t, %1; cvt.u32.u64 %0, t; }" : "=r"(a) : "l"(p));
    return a;
}
__device__ __forceinline__ uint32_t swz(uint32_t o) { return o ^ ((o >> 3) & 0x70); }

__device__ __forceinline__ void ldsm4(uint32_t r[4], uint32_t addr) {
    asm volatile("ldmatrix.sync.aligned.m8n8.x4.shared.b16 {%0,%1,%2,%3}, [%4];"
        : "=r"(r[0]), "=r"(r[1]), "=r"(r[2]), "=r"(r[3]) : "r"(addr));
}
__device__ __forceinline__ void ldsm4t(uint32_t r[4], uint32_t addr) {
    asm volatile("ldmatrix.sync.aligned.m8n8.x4.trans.shared.b16 {%0,%1,%2,%3}, [%4];"
        : "=r"(r[0]), "=r"(r[1]), "=r"(r[2]), "=r"(r[3]) : "r"(addr));
}
__device__ __forceinline__ void mma16816(float d[4], const uint32_t a[4], uint32_t b0, uint32_t b1) {
    asm volatile("mma.sync.aligned.m16n8k16.row.col.f32.f16.f16.f32 "
        "{%0,%1,%2,%3}, {%4,%5,%6,%7}, {%8,%9}, {%0,%1,%2,%3};"
        : "+f"(d[0]), "+f"(d[1]), "+f"(d[2]), "+f"(d[3])
        : "r"(a[0]), "r"(a[1]), "r"(a[2]), "r"(a[3]), "r"(b0), "r"(b1));
}
__device__ __forceinline__ void cp16(uint32_t dst, const void* src) {
    asm volatile("cp.async.cg.shared.global [%0], [%1], 16;" :: "r"(dst), "l"(src) : "memory");
}
#define CP_COMMIT() asm volatile("cp.async.commit_group;" ::: "memory")
#define CP_WAIT(n)  asm volatile("cp.async.wait_group %0;" :: "n"(n) : "memory")

// smem layout for body kernel
#define SM_WS   0          // 9 x 8192 = 73728
#define SM_HI0  73728
#define SM_HI1  97280
#define SM_LO0  120832
#define SM_LO1  144384
#define SMEM_BODY 167936

#define NTHR 256

// ---------------- weight prep: [l][b][tap][ic][oc], cw folded, fp16 ----------
__global__ void prep_kernel(const float* __restrict__ bw, float cw) {
    int idx = blockIdx.x * blockDim.x + threadIdx.x;
    const int N = 5 * 16 * 9 * 64 * 64;
    if (idx >= N) return;
    int oc = idx & 63;
    int ic = (idx >> 6) & 63;
    int tap = (idx >> 12) % 9;
    int rest = idx / (9 * 64 * 64);   // l*16+b
    float v = bw[(((size_t)rest * 64 + oc) * 64 + ic) * 9 + tap] * cw;
    g_wt[idx] = __float2half_rn(v);
}

// ---------------- head (scalar fp32, writes NHWC fp16 hi/lo) ----------------
__global__ __launch_bounds__(256)
void head_kernel(const float* __restrict__ noise, const float* __restrict__ hw,
                 const float* __restrict__ hb, __half* __restrict__ oh,
                 __half* __restrict__ ol, float cw, float cb)
{
    const int Sout = 268;
    int b = blockIdx.z >> 2;
    int oc0 = (blockIdx.z & 3) << 4;
    int tx0 = blockIdx.x * 32, ty0 = blockIdx.y * 8;
    int tid = threadIdx.x, tx = tid & 31, ty = tid >> 5;

    __shared__ __align__(16) float ws[3 * 9 * 16];
    __shared__ float xs[3 * 10 * 34];

    for (int i = tid; i < 3 * 144; i += 256) {
        int oc = i & 15, k = (i >> 4) % 9, ic = i / 144;
        ws[i] = hw[((b * 64 + oc0 + oc) * 3 + ic) * 9 + k];
    }
    for (int i = tid; i < 3 * 340; i += 256) {
        int ic = i / 340, rem = i % 340, r = rem / 34, c = rem % 34;
        int gy = ty0 + r - 7, gx = tx0 + c - 7;
        float v = 0.f;
        if (gy >= 0 && gy < 256 && gx >= 0 && gx < 256)
            v = noise[((size_t)(b * 3 + ic) * 256 + gy) * 256 + gx];
        xs[i] = v;
    }
    __syncthreads();

    float acc[16];
#pragma unroll
    for (int o = 0; o < 16; o++) acc[o] = 0.f;
#pragma unroll
    for (int ic = 0; ic < 3; ic++) {
        const float* xp = xs + ic * 340 + ty * 34 + tx;
        float xv[9];
#pragma unroll
        for (int ky = 0; ky < 3; ky++)
#pragma unroll
            for (int kx = 0; kx < 3; kx++) xv[ky * 3 + kx] = xp[ky * 34 + kx];
        const float4* wp = (const float4*)(ws + ic * 144);
#pragma unroll
        for (int k = 0; k < 9; k++) {
#pragma unroll
            for (int q = 0; q < 4; q++) {
                float4 w4 = wp[k * 4 + q];
                acc[q * 4 + 0] = fmaf(xv[k], w4.x, acc[q * 4 + 0]);
                acc[q * 4 + 1] = fmaf(xv[k], w4.y, acc[q * 4 + 1]);
                acc[q * 4 + 2] = fmaf(xv[k], w4.z, acc[q * 4 + 2]);
                acc[q * 4 + 3] = fmaf(xv[k], w4.w, acc[q * 4 + 3]);
            }
        }
    }

    int ox = tx0 + tx, oy = ty0 + ty;
    if (ox < Sout && oy < Sout) {
        __align__(16) __half h16[16], l16[16];
#pragma unroll
        for (int o = 0; o < 16; o++) {
            float v = acc[o] * cw + hb[b * 64 + oc0 + o] * cb;
            v = v > 0.f ? v : 0.02f * v;
            h16[o] = __float2half_rn(v);
            l16[o] = __float2half_rn(v - __half2float(h16[o]));
        }
        size_t obase = ((size_t)b * (Sout * Sout) + (size_t)oy * Sout + ox) * 64 + oc0;
        uint4* dh = (uint4*)(oh + obase);
        uint4* dl = (uint4*)(ol + obase);
        dh[0] = ((uint4*)h16)[0]; dh[1] = ((uint4*)h16)[1];
        dl[0] = ((uint4*)l16)[0]; dl[1] = ((uint4*)l16)[1];
    }
}

// ---------------- body A-slab gather via cp.async (hi+lo, one group) --------
__device__ __forceinline__ void gather_tile(uint32_t dstH, uint32_t dstL,
                                            const __half* __restrict__ srcH,
                                            const __half* __restrict__ srcL,
                                            int oy0, int ox0, int Sin, int tid)
{
    for (int i = tid; i < 1440; i += NTHR) {
        int e = i >> 3, q = i & 7;
        int er = e / 18, ec = e - er * 18;
        int iy = oy0 + er; if (iy > Sin - 1) iy = Sin - 1;
        int ix = ox0 + ec; if (ix > Sin - 1) ix = Sin - 1;
        size_t base = ((size_t)iy * Sin + ix) * 64 + q * 8;
        uint32_t off = swz((uint32_t)(e * 128 + q * 16));
        cp16(dstH + off, srcH + base);
        cp16(dstL + off, srcL + base);
    }
    CP_COMMIT();
}

// ---------------- body (mma.sync fp16 2-term split, fused phase) ------------
__global__ __launch_bounds__(NTHR, 1)
void body_mma_kernel(const __half* __restrict__ in_h,
                     const __half* __restrict__ in_l,
                     const __half* __restrict__ wt,     // [16][9][64 ic][64 oc]
                     const float* __restrict__ bias,    // [16][64]
                     __half* __restrict__ out_h,
                     __half* __restrict__ out_l,
                     int Sin, float cb)
{
    extern __shared__ __align__(1024) char smem[];
    const int Sout = Sin - 2;
    const int b = blockIdx.z, slot = blockIdx.x;
    const int tid = threadIdx.x, wid = tid >> 5, lane = tid & 31;
    const int wm = wid & 3, wn = wid >> 2;       // 4 x 2 warp grid, M32 x N32
    uint32_t sbase = smem_u32(smem);
    const uint32_t HI[2] = { sbase + SM_HI0, sbase + SM_HI1 };
    const uint32_t LO[2] = { sbase + SM_LO0, sbase + SM_LO1 };

    // stage weights: [tap][ic 64][128B oc], SW128-swizzled
    {
        const __half* wb = wt + (size_t)b * 9 * 4096;
        for (int i = tid; i < 4608; i += NTHR) {
            int j = i & 511, tap = i >> 9;
            int ic = j >> 3, q = j & 7;
            const uint4* src = (const uint4*)(wb + ((size_t)tap * 64 + ic) * 64) + q;
            *(uint4*)(smem + SM_WS + tap * 8192 + swz(ic * 128 + q * 16)) = *src;
        }
    }

    // per-thread bias: oc = wn*32 + j*8 + (lane&3)*2
    float bv[8];
#pragma unroll
    for (int j = 0; j < 4; j++) {
        int oc = wn * 32 + j * 8 + (lane & 3) * 2;
        bv[j * 2 + 0] = bias[b * 64 + oc] * cb;
        bv[j * 2 + 1] = bias[b * 64 + oc + 1] * cb;
    }

    const __half* ih = in_h + (size_t)b * Sin * Sin * 64;
    const __half* il = in_l + (size_t)b * Sin * Sin * 64;
    const int nrt = (Sout + 7) >> 3, nct = (Sout + 15) >> 4;
    const int ntiles = nrt * nct;
    const size_t Spo = (size_t)Sout * Sout;

    const int laneA = (lane & 15) * 128 + (lane >> 4) * 16;
    const int laneB = (lane & 15) * 128 + (lane >> 4) * 16 + wn * 64;

    int s = 0;
    // prologue: prefetch both slabs of first tile
    {
        int t0 = slot;
        if (t0 < ntiles) {
            int rt = t0 / nct, ct = t0 - rt * nct;
            gather_tile(HI[0], LO[0], ih, il, rt * 8, ct * 16, Sin, tid);
        } else {
            CP_COMMIT();
        }
    }

    for (int tt = slot; tt < ntiles; tt += 9) {
        int rt = tt / nct, ct = tt - rt * nct;
        int oy0 = rt * 8, ox0 = ct * 16;

        __syncthreads();                       // buffers s^1 no longer read
        int tn = tt + 9;
        if (tn < ntiles) {
            int rtn = tn / nct, ctn = tn - rtn * nct;
            gather_tile(HI[s ^ 1], LO[s ^ 1], ih, il, rtn * 8, ctn * 16, Sin, tid);
        } else {
            CP_COMMIT();
        }
        CP_WAIT(1); __syncthreads();           // tile t's slabs ready

        float acc[2][4][4];
#pragma unroll
        for (int mt = 0; mt < 2; mt++)
#pragma unroll
            for (int j = 0; j < 4; j++)
#pragma unroll
                for (int r = 0; r < 4; r++) acc[mt][j][r] = 0.f;

        // fused: (Ah + Al) * B
#pragma unroll
        for (int ky = 0; ky < 3; ky++) {
#pragma unroll
            for (int kx = 0; kx < 3; kx++) {
                uint32_t wtile = sbase + SM_WS + (ky * 3 + kx) * 8192;
#pragma unroll
                for (int kc = 0; kc < 4; kc++) {
                    uint32_t a_h[2][4], a_l[2][4];
#pragma unroll
                    for (int mt = 0; mt < 2; mt++) {
                        int ebase = ((wm * 2 + mt + ky) * 18 + kx) * 128 + kc * 32;
                        uint32_t off = swz((uint32_t)(ebase + laneA));
                        ldsm4(a_h[mt], HI[s] + off);
                        ldsm4(a_l[mt], LO[s] + off);
                    }
                    uint32_t bf[2][4];
#pragma unroll
                    for (int nt = 0; nt < 2; nt++) {
                        uint32_t off = swz((uint32_t)(kc * 2048 + laneB + nt * 32));
                        ldsm4t(bf[nt], wtile + off);
                    }
#pragma unroll
                    for (int mt = 0; mt < 2; mt++) {
#pragma unroll
                        for (int j = 0; j < 4; j++) {
                            uint32_t b0 = bf[j >> 1][(j & 1) * 2];
                            uint32_t b1 = bf[j >> 1][(j & 1) * 2 + 1];
                            mma16816(acc[mt][j], a_h[mt], b0, b1);
                            mma16816(acc[mt][j], a_l[mt], b0, b1);
                        }
                    }
                }
            }
        }

        // epilogue: bias + leaky, split fp16 hi/lo, store
#pragma unroll
        for (int mt = 0; mt < 2; mt++) {
            int oy = oy0 + wm * 2 + mt;
            if (oy >= Sout) continue;
#pragma unroll
            for (int rs = 0; rs < 2; rs++) {
                int c = (lane >> 2) + rs * 8;
                int ox = ox0 + c;
                if (ox >= Sout) continue;
                size_t pix = (size_t)oy * Sout + ox;
                size_t eoff = ((size_t)b * Spo + pix) * 64 + wn * 32 + (lane & 3) * 2;
#pragma unroll
                for (int j = 0; j < 4; j++) {
                    float v0 = acc[mt][j][rs * 2 + 0] + bv[j * 2 + 0];
                    float v1 = acc[mt][j][rs * 2 + 1] + bv[j * 2 + 1];
                    v0 = v0 > 0.f ? v0 : 0.02f * v0;
                    v1 = v1 > 0.f ? v1 : 0.02f * v1;
                    __half h0 = __float2half_rn(v0);
                    __half h1 = __float2half_rn(v1);
                    __half l0 = __float2half_rn(v0 - __half2float(h0));
                    __half l1 = __float2half_rn(v1 - __half2float(h1));
                    unsigned ph = (unsigned)__half_as_ushort(h0) | ((unsigned)__half_as_ushort(h1) << 16);
                    unsigned pl = (unsigned)__half_as_ushort(l0) | ((unsigned)__half_as_ushort(l1) << 16);
                    *(unsigned*)(out_h + eoff + j * 8) = ph;
                    *(unsigned*)(out_l + eoff + j * 8) = pl;
                }
            }
        }
        s ^= 1;
    }
}

// ---------------- tail (scalar, reads NHWC fp16 hi/lo) ----------------
__global__ __launch_bounds__(256)
void tail_kernel(const __half* __restrict__ in_h,
                 const __half* __restrict__ in_l,
                 const float* __restrict__ w, const float* __restrict__ bias,
                 float* __restrict__ out, float cw, float cb)
{
    extern __shared__ float sm[];
    float* ws = sm;              // 64*27
    float* xs = sm + 1728;       // 64 ic x 340 px
    const int Sin = 258, Sout = 256;
    int b = blockIdx.z;
    int tx0 = blockIdx.x * 32, ty0 = blockIdx.y * 8;
    int tid = threadIdx.x, tx = tid & 31, ty = tid >> 5;

    for (int i = tid; i < 64 * 27; i += 256) {
        int oc = i % 3, k = (i / 3) % 9, ic = i / 27;
        ws[i] = w[((b * 3 + oc) * 64 + ic) * 9 + k];
    }
    const __half* ihb = in_h + (size_t)b * Sin * Sin * 64;
    const __half* ilb = in_l + (size_t)b * Sin * Sin * 64;
    for (int i = tid; i < 2720; i += 256) {
        int p = i >> 3, g = i & 7;
        int py = p / 34, px = p - py * 34;
        size_t pb = ((size_t)(ty0 + py) * Sin + tx0 + px) * 64 + g * 8;
        uint4 H = *(const uint4*)(ihb + pb);
        uint4 L = *(const uint4*)(ilb + pb);
        const unsigned* hu = (const unsigned*)&H;
        const unsigned* lu = (const unsigned*)&L;
#pragma unroll
        for (int j = 0; j < 4; j++) {
            float2 fh = __half22float2(*(const __half2*)&hu[j]);
            float2 fl = __half22float2(*(const __half2*)&lu[j]);
            xs[(g * 8 + j * 2 + 0) * 340 + p] = fh.x + fl.x;
            xs[(g * 8 + j * 2 + 1) * 340 + p] = fh.y + fl.y;
        }
    }
    __syncthreads();

    float acc[3] = {0.f, 0.f, 0.f};
#pragma unroll 4
    for (int ic = 0; ic < 64; ic++) {
        const float* xp = xs + ic * 340 + ty * 34 + tx;
        float xv[9];
#pragma unroll
        for (int ky = 0; ky < 3; ky++)
#pragma unroll
            for (int kx = 0; kx < 3; kx++) xv[ky * 3 + kx] = xp[ky * 34 + kx];
        const float* wp = ws + ic * 27;
#pragma unroll
        for (int k = 0; k < 9; k++)
#pragma unroll
            for (int o = 0; o < 3; o++) acc[o] = fmaf(xv[k], wp[k * 3 + o], acc[o]);
    }

    int ox = tx0 + tx, oy = ty0 + ty;
    size_t obase = ((size_t)(b * 3)) * 65536 + (size_t)oy * 256 + ox;
#pragma unroll
    for (int o = 0; o < 3; o++)
        out[obase + (size_t)o * 65536] = tanhf(acc[o] * cw + bias[b * 3 + o] * cb);
}

// ---------------- launch ----------------
extern "C" void kernel_launch(void* const* d_in, const int* in_sizes, int n_in,
                              void* d_out, int out_size)
{
    const float* noise  = (const float*)d_in[0];
    const float* head_w = (const float*)d_in[1];
    const float* head_b = (const float*)d_in[2];
    const float* body_w = (const float*)d_in[3];
    const float* body_b = (const float*)d_in[4];
    const float* tail_w = (const float*)d_in[5];
    const float* tail_b = (const float*)d_in[6];
    float* out = (float*)d_out;

    __half *ah, *al, *bh, *bl, *wt;
    cudaGetSymbolAddress((void**)&ah, g_ah);
    cudaGetSymbolAddress((void**)&al, g_al);
    cudaGetSymbolAddress((void**)&bh, g_bh);
    cudaGetSymbolAddress((void**)&bl, g_bl);
    cudaGetSymbolAddress((void**)&wt, g_wt);

    cudaFuncSetAttribute(body_mma_kernel, cudaFuncAttributeMaxDynamicSharedMemorySize, SMEM_BODY);
    cudaFuncSetAttribute(tail_kernel, cudaFuncAttributeMaxDynamicSharedMemorySize, 94208);

    const double lr_gain = sqrt(2.0 / (1.0 + 0.02 * 0.02));
    const float cw_head = (float)(lr_gain / sqrt(27.0));
    const float cb_head = (float)(1.0 / sqrt(3.0));
    const float cw_body = (float)(lr_gain / 24.0);
    const float cb_body = 0.125f;
    const float cw_tail = (float)((5.0 / 3.0) / 24.0);
    const float cb_tail = 0.125f;

    // body weight prep (fold cw, fp16, k-major)
    {
        int N = 5 * 16 * 9 * 64 * 64;
        prep_kernel<<<(N + 255) / 256, 256>>>(body_w, cw_body);
    }

    // head -> (ah, al) (268)
    {
        dim3 grid((268 + 31) / 32, (268 + 7) / 8, BATCH * 4);
        head_kernel<<<grid, 256>>>(noise, head_w, head_b, ah, al, cw_head, cb_head);
    }

    // 5 body layers, ping-pong hi/lo buffers
    __half *sh = ah, *sl = al, *dh = bh, *dl = bl;
    int Sin = 268;
    for (int l = 0; l < 5; l++) {
        dim3 grid(9, 1, BATCH);
        const __half* wt_l = wt + (size_t)l * 16 * 9 * 4096;
        const float* bias_l = body_b + (size_t)l * 16 * 64;
        body_mma_kernel<<<grid, NTHR, SMEM_BODY>>>(sh, sl, wt_l, bias_l,
                                                   dh, dl, Sin, cb_body);
        __half* t;
        t = sh; sh = dh; dh = t;
        t = sl; sl = dl; dl = t;
        Sin -= 2;
    }

    // tail: (sh, sl) 258 -> out 256
    {
        dim3 grid(256 / 32, 256 / 8, BATCH);
        tail_kernel<<<grid, 256, 94208>>>(sh, sl, tail_w, tail_b, out, cw_tail, cb_tail);
    }
}

// round 9
// speedup vs baseline: 1.4522x; 1.0497x over previous
#include <cuda_runtime.h>
#include <cuda_fp16.h>
#include <math.h>
#include <stdint.h>

#define BATCH 16
#define MAXPIX (268u * 268u)

// activations NHWC fp16, separate hi/lo, ping-pong pairs
__device__ __half g_ah[16u * MAXPIX * 64u];
__device__ __half g_al[16u * MAXPIX * 64u];
__device__ __half g_bh[16u * MAXPIX * 64u];
__device__ __half g_bl[16u * MAXPIX * 64u];
// fp16 body weights, K-MAJOR: [5][16][tap 9][ic 64][oc 64]
__device__ __half g_wt[5u * 16u * 9u * 64u * 64u];
// fp16 tail weights: [16][tap 9][ic 64][oc 8(pad)]
__device__ __half g_twt[16u * 9u * 64u * 8u];

// ---------------- helpers ----------------
__device__ __forceinline__ uint32_t smem_u32(const void* p) {
    uint32_t a;
    asm("{ .reg .u64 t; cvta.to.shared.u64 t, %1; cvt.u32.u64 %0, t; }" : "=r"(a) : "l"(p));
    return a;
}
__device__ __forceinline__ uint32_t swz(uint32_t o) { return o ^ ((o >> 3) & 0x70); }

__device__ __forceinline__ void ldsm4(uint32_t r[4], uint32_t addr) {
    asm volatile("ldmatrix.sync.aligned.m8n8.x4.shared.b16 {%0,%1,%2,%3}, [%4];"
        : "=r"(r[0]), "=r"(r[1]), "=r"(r[2]), "=r"(r[3]) : "r"(addr));
}
__device__ __forceinline__ void ldsm4t(uint32_t r[4], uint32_t addr) {
    asm volatile("ldmatrix.sync.aligned.m8n8.x4.trans.shared.b16 {%0,%1,%2,%3}, [%4];"
        : "=r"(r[0]), "=r"(r[1]), "=r"(r[2]), "=r"(r[3]) : "r"(addr));
}
__device__ __forceinline__ void mma16816(float d[4], const uint32_t a[4], uint32_t b0, uint32_t b1) {
    asm volatile("mma.sync.aligned.m16n8k16.row.col.f32.f16.f16.f32 "
        "{%0,%1,%2,%3}, {%4,%5,%6,%7}, {%8,%9}, {%0,%1,%2,%3};"
        : "+f"(d[0]), "+f"(d[1]), "+f"(d[2]), "+f"(d[3])
        : "r"(a[0]), "r"(a[1]), "r"(a[2]), "r"(a[3]), "r"(b0), "r"(b1));
}
// fp16-accumulate variant (lo term): d/c are 2 regs of half2
__device__ __forceinline__ void mma16816h(uint32_t d[2], const uint32_t a[4], uint32_t b0, uint32_t b1) {
    asm volatile("mma.sync.aligned.m16n8k16.row.col.f16.f16.f16.f16 "
        "{%0,%1}, {%2,%3,%4,%5}, {%6,%7}, {%0,%1};"
        : "+r"(d[0]), "+r"(d[1])
        : "r"(a[0]), "r"(a[1]), "r"(a[2]), "r"(a[3]), "r"(b0), "r"(b1));
}
__device__ __forceinline__ void cp16(uint32_t dst, const void* src) {
    asm volatile("cp.async.cg.shared.global [%0], [%1], 16;" :: "r"(dst), "l"(src) : "memory");
}
#define CP_COMMIT() asm volatile("cp.async.commit_group;" ::: "memory")
#define CP_WAIT(n)  asm volatile("cp.async.wait_group %0;" :: "n"(n) : "memory")

// smem layout for body kernel
#define SM_WS   0          // 9 x 8192 = 73728
#define SM_HI0  73728
#define SM_HI1  97280
#define SM_LO0  120832
#define SM_LO1  144384
#define SMEM_BODY 167936

// smem layout for tail kernel
#define TSM_WS   0         // 9 x 1024 = 9216
#define TSM_HI0  9216
#define TSM_HI1  32768
#define TSM_LO0  56320
#define TSM_LO1  79872
#define SMEM_TAIL 103424

#define NTHR 256

// ---------------- weight prep: [l][b][tap][ic][oc], cw folded, fp16 ----------
__global__ void prep_kernel(const float* __restrict__ bw, float cw) {
    int idx = blockIdx.x * blockDim.x + threadIdx.x;
    const int N = 5 * 16 * 9 * 64 * 64;
    if (idx >= N) return;
    int oc = idx & 63;
    int ic = (idx >> 6) & 63;
    int tap = (idx >> 12) % 9;
    int rest = idx / (9 * 64 * 64);   // l*16+b
    float v = bw[(((size_t)rest * 64 + oc) * 64 + ic) * 9 + tap] * cw;
    g_wt[idx] = __float2half_rn(v);
}

// tail weights: [b][tap][ic][oc8], cw folded, oc>=3 zero
__global__ void prep_tail_kernel(const float* __restrict__ tw, float cw) {
    int idx = blockIdx.x * blockDim.x + threadIdx.x;
    const int N = 16 * 9 * 64 * 8;
    if (idx >= N) return;
    int oc = idx & 7;
    int ic = (idx >> 3) & 63;
    int tap = (idx >> 9) % 9;
    int b = idx / (9 * 64 * 8);
    float v = 0.f;
    if (oc < 3) v = tw[(((size_t)b * 3 + oc) * 64 + ic) * 9 + tap] * cw;
    g_twt[idx] = __float2half_rn(v);
}

// ---------------- head (scalar fp32, writes NHWC fp16 hi/lo) ----------------
__global__ __launch_bounds__(256)
void head_kernel(const float* __restrict__ noise, const float* __restrict__ hw,
                 const float* __restrict__ hb, __half* __restrict__ oh,
                 __half* __restrict__ ol, float cw, float cb)
{
    const int Sout = 268;
    int b = blockIdx.z >> 2;
    int oc0 = (blockIdx.z & 3) << 4;
    int tx0 = blockIdx.x * 32, ty0 = blockIdx.y * 8;
    int tid = threadIdx.x, tx = tid & 31, ty = tid >> 5;

    __shared__ __align__(16) float ws[3 * 9 * 16];
    __shared__ float xs[3 * 10 * 34];

    for (int i = tid; i < 3 * 144; i += 256) {
        int oc = i & 15, k = (i >> 4) % 9, ic = i / 144;
        ws[i] = hw[((b * 64 + oc0 + oc) * 3 + ic) * 9 + k];
    }
    for (int i = tid; i < 3 * 340; i += 256) {
        int ic = i / 340, rem = i % 340, r = rem / 34, c = rem % 34;
        int gy = ty0 + r - 7, gx = tx0 + c - 7;
        float v = 0.f;
        if (gy >= 0 && gy < 256 && gx >= 0 && gx < 256)
            v = noise[((size_t)(b * 3 + ic) * 256 + gy) * 256 + gx];
        xs[i] = v;
    }
    __syncthreads();

    float acc[16];
#pragma unroll
    for (int o = 0; o < 16; o++) acc[o] = 0.f;
#pragma unroll
    for (int ic = 0; ic < 3; ic++) {
        const float* xp = xs + ic * 340 + ty * 34 + tx;
        float xv[9];
#pragma unroll
        for (int ky = 0; ky < 3; ky++)
#pragma unroll
            for (int kx = 0; kx < 3; kx++) xv[ky * 3 + kx] = xp[ky * 34 + kx];
        const float4* wp = (const float4*)(ws + ic * 144);
#pragma unroll
        for (int k = 0; k < 9; k++) {
#pragma unroll
            for (int q = 0; q < 4; q++) {
                float4 w4 = wp[k * 4 + q];
                acc[q * 4 + 0] = fmaf(xv[k], w4.x, acc[q * 4 + 0]);
                acc[q * 4 + 1] = fmaf(xv[k], w4.y, acc[q * 4 + 1]);
                acc[q * 4 + 2] = fmaf(xv[k], w4.z, acc[q * 4 + 2]);
                acc[q * 4 + 3] = fmaf(xv[k], w4.w, acc[q * 4 + 3]);
            }
        }
    }

    int ox = tx0 + tx, oy = ty0 + ty;
    if (ox < Sout && oy < Sout) {
        __align__(16) __half h16[16], l16[16];
#pragma unroll
        for (int o = 0; o < 16; o++) {
            float v = acc[o] * cw + hb[b * 64 + oc0 + o] * cb;
            v = v > 0.f ? v : 0.02f * v;
            h16[o] = __float2half_rn(v);
            l16[o] = __float2half_rn(v - __half2float(h16[o]));
        }
        size_t obase = ((size_t)b * (Sout * Sout) + (size_t)oy * Sout + ox) * 64 + oc0;
        uint4* dh = (uint4*)(oh + obase);
        uint4* dl = (uint4*)(ol + obase);
        dh[0] = ((uint4*)h16)[0]; dh[1] = ((uint4*)h16)[1];
        dl[0] = ((uint4*)l16)[0]; dl[1] = ((uint4*)l16)[1];
    }
}

// ---------------- A-slab gather via cp.async (hi+lo, one group) --------------
__device__ __forceinline__ void gather_tile(uint32_t dstH, uint32_t dstL,
                                            const __half* __restrict__ srcH,
                                            const __half* __restrict__ srcL,
                                            int oy0, int ox0, int Sin, int tid)
{
    for (int i = tid; i < 1440; i += NTHR) {
        int e = i >> 3, q = i & 7;
        int er = e / 18, ec = e - er * 18;
        int iy = oy0 + er; if (iy > Sin - 1) iy = Sin - 1;
        int ix = ox0 + ec; if (ix > Sin - 1) ix = Sin - 1;
        size_t base = ((size_t)iy * Sin + ix) * 64 + q * 8;
        uint32_t off = swz((uint32_t)(e * 128 + q * 16));
        cp16(dstH + off, srcH + base);
        cp16(dstL + off, srcL + base);
    }
    CP_COMMIT();
}

// ---------------- body (fp16 2-term split: hi->f32acc, lo->f16acc) ----------
__global__ __launch_bounds__(NTHR, 1)
void body_mma_kernel(const __half* __restrict__ in_h,
                     const __half* __restrict__ in_l,
                     const __half* __restrict__ wt,     // [16][9][64 ic][64 oc]
                     const float* __restrict__ bias,    // [16][64]
                     __half* __restrict__ out_h,
                     __half* __restrict__ out_l,
                     int Sin, float cb)
{
    extern __shared__ __align__(1024) char smem[];
    const int Sout = Sin - 2;
    const int b = blockIdx.z, slot = blockIdx.x;
    const int tid = threadIdx.x, wid = tid >> 5, lane = tid & 31;
    const int wm = wid & 3, wn = wid >> 2;       // 4 x 2 warp grid, M32 x N32
    uint32_t sbase = smem_u32(smem);
    const uint32_t HI[2] = { sbase + SM_HI0, sbase + SM_HI1 };
    const uint32_t LO[2] = { sbase + SM_LO0, sbase + SM_LO1 };

    // stage weights: [tap][ic 64][128B oc], SW128-swizzled
    {
        const __half* wb = wt + (size_t)b * 9 * 4096;
        for (int i = tid; i < 4608; i += NTHR) {
            int j = i & 511, tap = i >> 9;
            int ic = j >> 3, q = j & 7;
            const uint4* src = (const uint4*)(wb + ((size_t)tap * 64 + ic) * 64) + q;
            *(uint4*)(smem + SM_WS + tap * 8192 + swz(ic * 128 + q * 16)) = *src;
        }
    }

    float bv[8];
#pragma unroll
    for (int j = 0; j < 4; j++) {
        int oc = wn * 32 + j * 8 + (lane & 3) * 2;
        bv[j * 2 + 0] = bias[b * 64 + oc] * cb;
        bv[j * 2 + 1] = bias[b * 64 + oc + 1] * cb;
    }

    const __half* ih = in_h + (size_t)b * Sin * Sin * 64;
    const __half* il = in_l + (size_t)b * Sin * Sin * 64;
    const int nrt = (Sout + 7) >> 3, nct = (Sout + 15) >> 4;
    const int ntiles = nrt * nct;
    const size_t Spo = (size_t)Sout * Sout;

    const int laneA = (lane & 15) * 128 + (lane >> 4) * 16;
    const int laneB = (lane & 15) * 128 + (lane >> 4) * 16 + wn * 64;

    int s = 0;
    {
        int t0 = slot;
        if (t0 < ntiles) {
            int rt = t0 / nct, ct = t0 - rt * nct;
            gather_tile(HI[0], LO[0], ih, il, rt * 8, ct * 16, Sin, tid);
        } else {
            CP_COMMIT();
        }
    }

    for (int tt = slot; tt < ntiles; tt += 9) {
        int rt = tt / nct, ct = tt - rt * nct;
        int oy0 = rt * 8, ox0 = ct * 16;

        __syncthreads();
        int tn = tt + 9;
        if (tn < ntiles) {
            int rtn = tn / nct, ctn = tn - rtn * nct;
            gather_tile(HI[s ^ 1], LO[s ^ 1], ih, il, rtn * 8, ctn * 16, Sin, tid);
        } else {
            CP_COMMIT();
        }
        CP_WAIT(1); __syncthreads();

        float acc[2][4][4];
        uint32_t accl[2][4][2];
#pragma unroll
        for (int mt = 0; mt < 2; mt++)
#pragma unroll
            for (int j = 0; j < 4; j++) {
#pragma unroll
                for (int r = 0; r < 4; r++) acc[mt][j][r] = 0.f;
                accl[mt][j][0] = 0u; accl[mt][j][1] = 0u;
            }

#pragma unroll
        for (int ky = 0; ky < 3; ky++) {
#pragma unroll
            for (int kx = 0; kx < 3; kx++) {
                uint32_t wtile = sbase + SM_WS + (ky * 3 + kx) * 8192;
#pragma unroll
                for (int kc = 0; kc < 4; kc++) {
                    uint32_t a_h[2][4], a_l[2][4];
#pragma unroll
                    for (int mt = 0; mt < 2; mt++) {
                        int ebase = ((wm * 2 + mt + ky) * 18 + kx) * 128 + kc * 32;
                        uint32_t off = swz((uint32_t)(ebase + laneA));
                        ldsm4(a_h[mt], HI[s] + off);
                        ldsm4(a_l[mt], LO[s] + off);
                    }
                    uint32_t bf[2][4];
#pragma unroll
                    for (int nt = 0; nt < 2; nt++) {
                        uint32_t off = swz((uint32_t)(kc * 2048 + laneB + nt * 32));
                        ldsm4t(bf[nt], wtile + off);
                    }
#pragma unroll
                    for (int mt = 0; mt < 2; mt++) {
#pragma unroll
                        for (int j = 0; j < 4; j++) {
                            uint32_t b0 = bf[j >> 1][(j & 1) * 2];
                            uint32_t b1 = bf[j >> 1][(j & 1) * 2 + 1];
                            mma16816(acc[mt][j], a_h[mt], b0, b1);
                            mma16816h(accl[mt][j], a_l[mt], b0, b1);
                        }
                    }
                }
            }
        }

        // epilogue: combine hi+lo, bias + leaky, split fp16 hi/lo, store
#pragma unroll
        for (int mt = 0; mt < 2; mt++) {
            int oy = oy0 + wm * 2 + mt;
            if (oy >= Sout) continue;
#pragma unroll
            for (int rs = 0; rs < 2; rs++) {
                int c = (lane >> 2) + rs * 8;
                int ox = ox0 + c;
                if (ox >= Sout) continue;
                size_t pix = (size_t)oy * Sout + ox;
                size_t eoff = ((size_t)b * Spo + pix) * 64 + wn * 32 + (lane & 3) * 2;
#pragma unroll
                for (int j = 0; j < 4; j++) {
                    float2 lo2 = __half22float2(*(const __half2*)&accl[mt][j][rs]);
                    float v0 = acc[mt][j][rs * 2 + 0] + lo2.x + bv[j * 2 + 0];
                    float v1 = acc[mt][j][rs * 2 + 1] + lo2.y + bv[j * 2 + 1];
                    v0 = v0 > 0.f ? v0 : 0.02f * v0;
                    v1 = v1 > 0.f ? v1 : 0.02f * v1;
                    __half h0 = __float2half_rn(v0);
                    __half h1 = __float2half_rn(v1);
                    __half l0 = __float2half_rn(v0 - __half2float(h0));
                    __half l1 = __float2half_rn(v1 - __half2float(h1));
                    unsigned ph = (unsigned)__half_as_ushort(h0) | ((unsigned)__half_as_ushort(h1) << 16);
                    unsigned pl = (unsigned)__half_as_ushort(l0) | ((unsigned)__half_as_ushort(l1) << 16);
                    *(unsigned*)(out_h + eoff + j * 8) = ph;
                    *(unsigned*)(out_l + eoff + j * 8) = pl;
                }
            }
        }
        s ^= 1;
    }
}

// ---------------- tail (mma, N=8 padded from 3, tanh epilogue) ---------------
__global__ __launch_bounds__(NTHR, 2)
void tail_mma_kernel(const __half* __restrict__ in_h,
                     const __half* __restrict__ in_l,
                     const float* __restrict__ bias,    // [16][3]
                     float* __restrict__ out, float cb)
{
    extern __shared__ __align__(1024) char smem[];
    const int Sin = 258, Sout = 256;
    const int b = blockIdx.z, slot = blockIdx.x, nslots = gridDim.x;
    const int tid = threadIdx.x, wid = tid >> 5, lane = tid & 31;
    uint32_t sbase = smem_u32(smem);
    const uint32_t HI[2] = { sbase + TSM_HI0, sbase + TSM_HI1 };
    const uint32_t LO[2] = { sbase + TSM_LO0, sbase + TSM_LO1 };

    // stage tail weights: [tap][ic 64][oc8] fp16, 16B rows, no swizzle
    {
        const __half* wb = g_twt + (size_t)b * 9 * 512;
        for (int i = tid; i < 576; i += NTHR) {   // 9*64 rows of 16B
            *(uint4*)(smem + TSM_WS + i * 16) = *((const uint4*)wb + i);
        }
    }

    const __half* ih = in_h + (size_t)b * Sin * Sin * 64;
    const __half* il = in_l + (size_t)b * Sin * Sin * 64;
    const int nct = 16, ntiles = 32 * 16;    // 8x16 px tiles over 256x256

    const int laneA = (lane & 15) * 128 + (lane >> 4) * 16;

    int s = 0;
    {
        int t0 = slot;
        if (t0 < ntiles) {
            int rt = t0 / nct, ct = t0 - rt * nct;
            gather_tile(HI[0], LO[0], ih, il, rt * 8, ct * 16, Sin, tid);
        } else {
            CP_COMMIT();
        }
    }

    for (int tt = slot; tt < ntiles; tt += nslots) {
        int rt = tt / nct, ct = tt - rt * nct;
        int oy0 = rt * 8, ox0 = ct * 16;

        __syncthreads();
        int tn = tt + nslots;
        if (tn < ntiles) {
            int rtn = tn / nct, ctn = tn - rtn * nct;
            gather_tile(HI[s ^ 1], LO[s ^ 1], ih, il, rtn * 8, ctn * 16, Sin, tid);
        } else {
            CP_COMMIT();
        }
        CP_WAIT(1); __syncthreads();

        float acc[4] = {0.f, 0.f, 0.f, 0.f};
        uint32_t accl[2] = {0u, 0u};

        // warp wid handles output row oy0+wid; m16 = 16 px of that row
#pragma unroll
        for (int ky = 0; ky < 3; ky++) {
#pragma unroll
            for (int kx = 0; kx < 3; kx++) {
                uint32_t wtap = sbase + TSM_WS + (ky * 3 + kx) * 1024;
#pragma unroll
                for (int kh = 0; kh < 2; kh++) {
                    uint32_t bf[4];
                    ldsm4t(bf, wtap + kh * 512 + lane * 16);
#pragma unroll
                    for (int wh = 0; wh < 2; wh++) {
                        int kc = kh * 2 + wh;
                        int ebase = ((wid + ky) * 18 + kx) * 128 + kc * 32;
                        uint32_t off = swz((uint32_t)(ebase + laneA));
                        uint32_t a_h[4], a_l[4];
                        ldsm4(a_h, HI[s] + off);
                        ldsm4(a_l, LO[s] + off);
                        mma16816(acc, a_h, bf[wh * 2], bf[wh * 2 + 1]);
                        mma16816h(accl, a_l, bf[wh * 2], bf[wh * 2 + 1]);
                    }
                }
            }
        }

        // epilogue: tanh(acc + lo + bias), oc = (lane&3)*2, +1 (valid < 3)
        {
            int oy = oy0 + wid;
            int oc0 = (lane & 3) * 2;
            float2 lo0 = __half22float2(*(const __half2*)&accl[0]);
            float2 lo1 = __half22float2(*(const __half2*)&accl[1]);
            if (oc0 < 3) {
                int p0 = lane >> 2;
#pragma unroll
                for (int rs = 0; rs < 2; rs++) {
                    int ox = ox0 + p0 + rs * 8;
                    float lx = rs ? lo1.x : lo0.x;
                    float ly = rs ? lo1.y : lo0.y;
                    float v0 = acc[rs * 2 + 0] + lx + bias[b * 3 + oc0] * cb;
                    out[((size_t)(b * 3 + oc0) * Sout + oy) * Sout + ox] = tanhf(v0);
                    if (oc0 + 1 < 3) {
                        float v1 = acc[rs * 2 + 1] + ly + bias[b * 3 + oc0 + 1] * cb;
                        out[((size_t)(b * 3 + oc0 + 1) * Sout + oy) * Sout + ox] = tanhf(v1);
                    }
                }
            }
        }
        s ^= 1;
    }
}

// ---------------- launch ----------------
extern "C" void kernel_launch(void* const* d_in, const int* in_sizes, int n_in,
                              void* d_out, int out_size)
{
    const float* noise  = (const float*)d_in[0];
    const float* head_w = (const float*)d_in[1];
    const float* head_b = (const float*)d_in[2];
    const float* body_w = (const float*)d_in[3];
    const float* body_b = (const float*)d_in[4];
    const float* tail_w = (const float*)d_in[5];
    const float* tail_b = (const float*)d_in[6];
    float* out = (float*)d_out;

    __half *ah, *al, *bh, *bl, *wt;
    cudaGetSymbolAddress((void**)&ah, g_ah);
    cudaGetSymbolAddress((void**)&al, g_al);
    cudaGetSymbolAddress((void**)&bh, g_bh);
    cudaGetSymbolAddress((void**)&bl, g_bl);
    cudaGetSymbolAddress((void**)&wt, g_wt);

    cudaFuncSetAttribute(body_mma_kernel, cudaFuncAttributeMaxDynamicSharedMemorySize, SMEM_BODY);
    cudaFuncSetAttribute(tail_mma_kernel, cudaFuncAttributeMaxDynamicSharedMemorySize, SMEM_TAIL);

    const double lr_gain = sqrt(2.0 / (1.0 + 0.02 * 0.02));
    const float cw_head = (float)(lr_gain / sqrt(27.0));
    const float cb_head = (float)(1.0 / sqrt(3.0));
    const float cw_body = (float)(lr_gain / 24.0);
    const float cb_body = 0.125f;
    const float cw_tail = (float)((5.0 / 3.0) / 24.0);
    const float cb_tail = 0.125f;

    // weight preps (fold cw, fp16, k-major)
    {
        int N = 5 * 16 * 9 * 64 * 64;
        prep_kernel<<<(N + 255) / 256, 256>>>(body_w, cw_body);
        int M = 16 * 9 * 64 * 8;
        prep_tail_kernel<<<(M + 255) / 256, 256>>>(tail_w, cw_tail);
    }

    // head -> (ah, al) (268)
    {
        dim3 grid((268 + 31) / 32, (268 + 7) / 8, BATCH * 4);
        head_kernel<<<grid, 256>>>(noise, head_w, head_b, ah, al, cw_head, cb_head);
    }

    // 5 body layers, ping-pong hi/lo buffers
    __half *sh = ah, *sl = al, *dh = bh, *dl = bl;
    int Sin = 268;
    for (int l = 0; l < 5; l++) {
        dim3 grid(9, 1, BATCH);
        const __half* wt_l = wt + (size_t)l * 16 * 9 * 4096;
        const float* bias_l = body_b + (size_t)l * 16 * 64;
        body_mma_kernel<<<grid, NTHR, SMEM_BODY>>>(sh, sl, wt_l, bias_l,
                                                   dh, dl, Sin, cb_body);
        __half* t;
        t = sh; sh = dh; dh = t;
        t = sl; sl = dl; dl = t;
        Sin -= 2;
    }

    // tail (tensorized): (sh, sl) 258 -> out 256
    {
        dim3 grid(36, 1, BATCH);
        tail_mma_kernel<<<grid, NTHR, SMEM_TAIL>>>(sh, sl, tail_b, out, cb_tail);
    }
}

// round 10
// speedup vs baseline: 2.5105x; 1.7287x over previous
#include <cuda_runtime.h>
#include <cuda_fp16.h>
#include <math.h>
#include <stdint.h>

#define BATCH 16
#define MAXPIX (268u * 268u)

// activations NHWC fp16 (single precision-term), ping-pong
__device__ __half g_actA[16u * MAXPIX * 64u];
__device__ __half g_actB[16u * MAXPIX * 64u];
// fp16 body weights, K-MAJOR: [5][16][tap 9][ic 64][oc 64]
__device__ __half g_wt[5u * 16u * 9u * 64u * 64u];
// fp16 tail weights: [16][tap 9][ic 64][oc 8(pad)]
__device__ __half g_twt[16u * 9u * 64u * 8u];

// ---------------- helpers ----------------
__device__ __forceinline__ uint32_t smem_u32(const void* p) {
    uint32_t a;
    asm("{ .reg .u64 t; cvta.to.shared.u64 t, %1; cvt.u32.u64 %0, t; }" : "=r"(a) : "l"(p));
    return a;
}
__device__ __forceinline__ uint32_t swz(uint32_t o) { return o ^ ((o >> 3) & 0x70); }

__device__ __forceinline__ void ldsm4(uint32_t r[4], uint32_t addr) {
    asm volatile("ldmatrix.sync.aligned.m8n8.x4.shared.b16 {%0,%1,%2,%3}, [%4];"
        : "=r"(r[0]), "=r"(r[1]), "=r"(r[2]), "=r"(r[3]) : "r"(addr));
}
__device__ __forceinline__ void ldsm4t(uint32_t r[4], uint32_t addr) {
    asm volatile("ldmatrix.sync.aligned.m8n8.x4.trans.shared.b16 {%0,%1,%2,%3}, [%4];"
        : "=r"(r[0]), "=r"(r[1]), "=r"(r[2]), "=r"(r[3]) : "r"(addr));
}
__device__ __forceinline__ void mma16816(float d[4], const uint32_t a[4], uint32_t b0, uint32_t b1) {
    asm volatile("mma.sync.aligned.m16n8k16.row.col.f32.f16.f16.f32 "
        "{%0,%1,%2,%3}, {%4,%5,%6,%7}, {%8,%9}, {%0,%1,%2,%3};"
        : "+f"(d[0]), "+f"(d[1]), "+f"(d[2]), "+f"(d[3])
        : "r"(a[0]), "r"(a[1]), "r"(a[2]), "r"(a[3]), "r"(b0), "r"(b1));
}
__device__ __forceinline__ void cp16(uint32_t dst, const void* src) {
    asm volatile("cp.async.cg.shared.global [%0], [%1], 16;" :: "r"(dst), "l"(src) : "memory");
}
#define CP_COMMIT() asm volatile("cp.async.commit_group;" ::: "memory")
#define CP_WAIT(n)  asm volatile("cp.async.wait_group %0;" :: "n"(n) : "memory")

// smem layout for body kernel
#define SM_WS   0          // 9 x 8192 = 73728
#define SM_A0   73728
#define SM_A1   97280
#define SMEM_BODY 120832

// smem layout for tail kernel
#define TSM_WS  0          // 9 x 1024 = 9216
#define TSM_A0  9216
#define TSM_A1  32768
#define SMEM_TAIL 56320

#define NTHR 256

// ---------------- weight prep: [l][b][tap][ic][oc], cw folded, fp16 ----------
__global__ void prep_kernel(const float* __restrict__ bw, float cw) {
    int idx = blockIdx.x * blockDim.x + threadIdx.x;
    const int N = 5 * 16 * 9 * 64 * 64;
    if (idx >= N) return;
    int oc = idx & 63;
    int ic = (idx >> 6) & 63;
    int tap = (idx >> 12) % 9;
    int rest = idx / (9 * 64 * 64);   // l*16+b
    float v = bw[(((size_t)rest * 64 + oc) * 64 + ic) * 9 + tap] * cw;
    g_wt[idx] = __float2half_rn(v);
}

// tail weights: [b][tap][ic][oc8], cw folded, oc>=3 zero
__global__ void prep_tail_kernel(const float* __restrict__ tw, float cw) {
    int idx = blockIdx.x * blockDim.x + threadIdx.x;
    const int N = 16 * 9 * 64 * 8;
    if (idx >= N) return;
    int oc = idx & 7;
    int ic = (idx >> 3) & 63;
    int tap = (idx >> 9) % 9;
    int b = idx / (9 * 64 * 8);
    float v = 0.f;
    if (oc < 3) v = tw[(((size_t)b * 3 + oc) * 64 + ic) * 9 + tap] * cw;
    g_twt[idx] = __float2half_rn(v);
}

// ---------------- head (scalar fp32, writes NHWC fp16) ----------------
__global__ __launch_bounds__(256)
void head_kernel(const float* __restrict__ noise, const float* __restrict__ hw,
                 const float* __restrict__ hb, __half* __restrict__ oh,
                 float cw, float cb)
{
    const int Sout = 268;
    int b = blockIdx.z >> 2;
    int oc0 = (blockIdx.z & 3) << 4;
    int tx0 = blockIdx.x * 32, ty0 = blockIdx.y * 8;
    int tid = threadIdx.x, tx = tid & 31, ty = tid >> 5;

    __shared__ __align__(16) float ws[3 * 9 * 16];
    __shared__ float xs[3 * 10 * 34];

    for (int i = tid; i < 3 * 144; i += 256) {
        int oc = i & 15, k = (i >> 4) % 9, ic = i / 144;
        ws[i] = hw[((b * 64 + oc0 + oc) * 3 + ic) * 9 + k];
    }
    for (int i = tid; i < 3 * 340; i += 256) {
        int ic = i / 340, rem = i % 340, r = rem / 34, c = rem % 34;
        int gy = ty0 + r - 7, gx = tx0 + c - 7;
        float v = 0.f;
        if (gy >= 0 && gy < 256 && gx >= 0 && gx < 256)
            v = noise[((size_t)(b * 3 + ic) * 256 + gy) * 256 + gx];
        xs[i] = v;
    }
    __syncthreads();

    float acc[16];
#pragma unroll
    for (int o = 0; o < 16; o++) acc[o] = 0.f;
#pragma unroll
    for (int ic = 0; ic < 3; ic++) {
        const float* xp = xs + ic * 340 + ty * 34 + tx;
        float xv[9];
#pragma unroll
        for (int ky = 0; ky < 3; ky++)
#pragma unroll
            for (int kx = 0; kx < 3; kx++) xv[ky * 3 + kx] = xp[ky * 34 + kx];
        const float4* wp = (const float4*)(ws + ic * 144);
#pragma unroll
        for (int k = 0; k < 9; k++) {
#pragma unroll
            for (int q = 0; q < 4; q++) {
                float4 w4 = wp[k * 4 + q];
                acc[q * 4 + 0] = fmaf(xv[k], w4.x, acc[q * 4 + 0]);
                acc[q * 4 + 1] = fmaf(xv[k], w4.y, acc[q * 4 + 1]);
                acc[q * 4 + 2] = fmaf(xv[k], w4.z, acc[q * 4 + 2]);
                acc[q * 4 + 3] = fmaf(xv[k], w4.w, acc[q * 4 + 3]);
            }
        }
    }

    int ox = tx0 + tx, oy = ty0 + ty;
    if (ox < Sout && oy < Sout) {
        __align__(16) __half h16[16];
#pragma unroll
        for (int o = 0; o < 16; o++) {
            float v = acc[o] * cw + hb[b * 64 + oc0 + o] * cb;
            v = v > 0.f ? v : 0.02f * v;
            h16[o] = __float2half_rn(v);
        }
        size_t obase = ((size_t)b * (Sout * Sout) + (size_t)oy * Sout + ox) * 64 + oc0;
        uint4* dh = (uint4*)(oh + obase);
        dh[0] = ((uint4*)h16)[0]; dh[1] = ((uint4*)h16)[1];
    }
}

// ---------------- A-slab gather via cp.async (single buffer) -----------------
__device__ __forceinline__ void gather_tile(uint32_t dst,
                                            const __half* __restrict__ src,
                                            int oy0, int ox0, int Sin, int tid)
{
    // slab: 10 rows x 18 px x 64 ch fp16 = 1440 16B chunks, SW128 swizzled
    for (int i = tid; i < 1440; i += NTHR) {
        int e = i >> 3, q = i & 7;
        int er = e / 18, ec = e - er * 18;
        int iy = oy0 + er; if (iy > Sin - 1) iy = Sin - 1;
        int ix = ox0 + ec; if (ix > Sin - 1) ix = Sin - 1;
        size_t base = ((size_t)iy * Sin + ix) * 64 + q * 8;
        cp16(dst + swz((uint32_t)(e * 128 + q * 16)), src + base);
    }
    CP_COMMIT();
}

// ---------------- body (mma.sync fp16 single-term) ----------------
__global__ __launch_bounds__(NTHR, 1)
void body_mma_kernel(const __half* __restrict__ in_a,
                     const __half* __restrict__ wt,     // [16][9][64 ic][64 oc]
                     const float* __restrict__ bias,    // [16][64]
                     __half* __restrict__ out_a,
                     int Sin, float cb)
{
    extern __shared__ __align__(1024) char smem[];
    const int Sout = Sin - 2;
    const int b = blockIdx.z, slot = blockIdx.x;
    const int tid = threadIdx.x, wid = tid >> 5, lane = tid & 31;
    const int wm = wid & 3, wn = wid >> 2;       // 4 x 2 warp grid, M32 x N32
    uint32_t sbase = smem_u32(smem);
    const uint32_t A[2] = { sbase + SM_A0, sbase + SM_A1 };

    // stage weights: [tap][ic 64][128B oc], SW128-swizzled
    {
        const __half* wb = wt + (size_t)b * 9 * 4096;
        for (int i = tid; i < 4608; i += NTHR) {
            int j = i & 511, tap = i >> 9;
            int ic = j >> 3, q = j & 7;
            const uint4* src = (const uint4*)(wb + ((size_t)tap * 64 + ic) * 64) + q;
            *(uint4*)(smem + SM_WS + tap * 8192 + swz(ic * 128 + q * 16)) = *src;
        }
    }

    float bv[8];
#pragma unroll
    for (int j = 0; j < 4; j++) {
        int oc = wn * 32 + j * 8 + (lane & 3) * 2;
        bv[j * 2 + 0] = bias[b * 64 + oc] * cb;
        bv[j * 2 + 1] = bias[b * 64 + oc + 1] * cb;
    }

    const __half* ia = in_a + (size_t)b * Sin * Sin * 64;
    const int nrt = (Sout + 7) >> 3, nct = (Sout + 15) >> 4;
    const int ntiles = nrt * nct;
    const size_t Spo = (size_t)Sout * Sout;

    const int laneA = (lane & 15) * 128 + (lane >> 4) * 16;
    const int laneB = (lane & 15) * 128 + (lane >> 4) * 16 + wn * 64;

    int s = 0;
    {
        int t0 = slot;
        if (t0 < ntiles) {
            int rt = t0 / nct, ct = t0 - rt * nct;
            gather_tile(A[0], ia, rt * 8, ct * 16, Sin, tid);
        } else {
            CP_COMMIT();
        }
    }

    for (int tt = slot; tt < ntiles; tt += 9) {
        int rt = tt / nct, ct = tt - rt * nct;
        int oy0 = rt * 8, ox0 = ct * 16;

        __syncthreads();
        int tn = tt + 9;
        if (tn < ntiles) {
            int rtn = tn / nct, ctn = tn - rtn * nct;
            gather_tile(A[s ^ 1], ia, rtn * 8, ctn * 16, Sin, tid);
        } else {
            CP_COMMIT();
        }
        CP_WAIT(1); __syncthreads();

        float acc[2][4][4];
#pragma unroll
        for (int mt = 0; mt < 2; mt++)
#pragma unroll
            for (int j = 0; j < 4; j++)
#pragma unroll
                for (int r = 0; r < 4; r++) acc[mt][j][r] = 0.f;

#pragma unroll
        for (int ky = 0; ky < 3; ky++) {
#pragma unroll
            for (int kx = 0; kx < 3; kx++) {
                uint32_t wtile = sbase + SM_WS + (ky * 3 + kx) * 8192;
#pragma unroll
                for (int kc = 0; kc < 4; kc++) {
                    uint32_t a_f[2][4];
#pragma unroll
                    for (int mt = 0; mt < 2; mt++) {
                        int ebase = ((wm * 2 + mt + ky) * 18 + kx) * 128 + kc * 32;
                        ldsm4(a_f[mt], A[s] + swz((uint32_t)(ebase + laneA)));
                    }
                    uint32_t bf[2][4];
#pragma unroll
                    for (int nt = 0; nt < 2; nt++) {
                        uint32_t off = swz((uint32_t)(kc * 2048 + laneB + nt * 32));
                        ldsm4t(bf[nt], wtile + off);
                    }
#pragma unroll
                    for (int mt = 0; mt < 2; mt++) {
#pragma unroll
                        for (int j = 0; j < 4; j++) {
                            uint32_t b0 = bf[j >> 1][(j & 1) * 2];
                            uint32_t b1 = bf[j >> 1][(j & 1) * 2 + 1];
                            mma16816(acc[mt][j], a_f[mt], b0, b1);
                        }
                    }
                }
            }
        }

        // epilogue: bias + leaky, store fp16
#pragma unroll
        for (int mt = 0; mt < 2; mt++) {
            int oy = oy0 + wm * 2 + mt;
            if (oy >= Sout) continue;
#pragma unroll
            for (int rs = 0; rs < 2; rs++) {
                int c = (lane >> 2) + rs * 8;
                int ox = ox0 + c;
                if (ox >= Sout) continue;
                size_t pix = (size_t)oy * Sout + ox;
                size_t eoff = ((size_t)b * Spo + pix) * 64 + wn * 32 + (lane & 3) * 2;
#pragma unroll
                for (int j = 0; j < 4; j++) {
                    float v0 = acc[mt][j][rs * 2 + 0] + bv[j * 2 + 0];
                    float v1 = acc[mt][j][rs * 2 + 1] + bv[j * 2 + 1];
                    v0 = v0 > 0.f ? v0 : 0.02f * v0;
                    v1 = v1 > 0.f ? v1 : 0.02f * v1;
                    __half h0 = __float2half_rn(v0);
                    __half h1 = __float2half_rn(v1);
                    unsigned ph = (unsigned)__half_as_ushort(h0) | ((unsigned)__half_as_ushort(h1) << 16);
                    *(unsigned*)(out_a + eoff + j * 8) = ph;
                }
            }
        }
        s ^= 1;
    }
}

// ---------------- tail (mma, N=8 padded from 3, tanh epilogue) ---------------
__global__ __launch_bounds__(NTHR, 2)
void tail_mma_kernel(const __half* __restrict__ in_a,
                     const float* __restrict__ bias,    // [16][3]
                     float* __restrict__ out, float cb)
{
    extern __shared__ __align__(1024) char smem[];
    const int Sin = 258, Sout = 256;
    const int b = blockIdx.z, slot = blockIdx.x, nslots = gridDim.x;
    const int tid = threadIdx.x, wid = tid >> 5, lane = tid & 31;
    uint32_t sbase = smem_u32(smem);
    const uint32_t A[2] = { sbase + TSM_A0, sbase + TSM_A1 };

    // stage tail weights: [tap][ic 64][oc8] fp16, 16B rows
    {
        const __half* wb = g_twt + (size_t)b * 9 * 512;
        for (int i = tid; i < 576; i += NTHR) {
            *(uint4*)(smem + TSM_WS + i * 16) = *((const uint4*)wb + i);
        }
    }

    const __half* ia = in_a + (size_t)b * Sin * Sin * 64;
    const int nct = 16, ntiles = 32 * 16;    // 8x16 px tiles over 256x256

    const int laneA = (lane & 15) * 128 + (lane >> 4) * 16;

    int s = 0;
    {
        int t0 = slot;
        if (t0 < ntiles) {
            int rt = t0 / nct, ct = t0 - rt * nct;
            gather_tile(A[0], ia, rt * 8, ct * 16, Sin, tid);
        } else {
            CP_COMMIT();
        }
    }

    for (int tt = slot; tt < ntiles; tt += nslots) {
        int rt = tt / nct, ct = tt - rt * nct;
        int oy0 = rt * 8, ox0 = ct * 16;

        __syncthreads();
        int tn = tt + nslots;
        if (tn < ntiles) {
            int rtn = tn / nct, ctn = tn - rtn * nct;
            gather_tile(A[s ^ 1], ia, rtn * 8, ctn * 16, Sin, tid);
        } else {
            CP_COMMIT();
        }
        CP_WAIT(1); __syncthreads();

        float acc[4] = {0.f, 0.f, 0.f, 0.f};

        // warp wid handles output row oy0+wid; m16 = 16 px of that row
#pragma unroll
        for (int ky = 0; ky < 3; ky++) {
#pragma unroll
            for (int kx = 0; kx < 3; kx++) {
                uint32_t wtap = sbase + TSM_WS + (ky * 3 + kx) * 1024;
#pragma unroll
                for (int kh = 0; kh < 2; kh++) {
                    uint32_t bf[4];
                    ldsm4t(bf, wtap + kh * 512 + lane * 16);
#pragma unroll
                    for (int wh = 0; wh < 2; wh++) {
                        int kc = kh * 2 + wh;
                        int ebase = ((wid + ky) * 18 + kx) * 128 + kc * 32;
                        uint32_t a_f[4];
                        ldsm4(a_f, A[s] + swz((uint32_t)(ebase + laneA)));
                        mma16816(acc, a_f, bf[wh * 2], bf[wh * 2 + 1]);
                    }
                }
            }
        }

        // epilogue: tanh(acc + bias), oc = (lane&3)*2 (+1), valid oc < 3
        {
            int oy = oy0 + wid;
            int oc0 = (lane & 3) * 2;
            if (oc0 < 3) {
                int p0 = lane >> 2;
#pragma unroll
                for (int rs = 0; rs < 2; rs++) {
                    int ox = ox0 + p0 + rs * 8;
                    float v0 = acc[rs * 2 + 0] + bias[b * 3 + oc0] * cb;
                    out[((size_t)(b * 3 + oc0) * Sout + oy) * Sout + ox] = tanhf(v0);
                    if (oc0 + 1 < 3) {
                        float v1 = acc[rs * 2 + 1] + bias[b * 3 + oc0 + 1] * cb;
                        out[((size_t)(b * 3 + oc0 + 1) * Sout + oy) * Sout + ox] = tanhf(v1);
                    }
                }
            }
        }
        s ^= 1;
    }
}

// ---------------- launch ----------------
extern "C" void kernel_launch(void* const* d_in, const int* in_sizes, int n_in,
                              void* d_out, int out_size)
{
    const float* noise  = (const float*)d_in[0];
    const float* head_w = (const float*)d_in[1];
    const float* head_b = (const float*)d_in[2];
    const float* body_w = (const float*)d_in[3];
    const float* body_b = (const float*)d_in[4];
    const float* tail_w = (const float*)d_in[5];
    const float* tail_b = (const float*)d_in[6];
    float* out = (float*)d_out;

    __half *actA, *actB, *wt;
    cudaGetSymbolAddress((void**)&actA, g_actA);
    cudaGetSymbolAddress((void**)&actB, g_actB);
    cudaGetSymbolAddress((void**)&wt, g_wt);

    cudaFuncSetAttribute(body_mma_kernel, cudaFuncAttributeMaxDynamicSharedMemorySize, SMEM_BODY);
    cudaFuncSetAttribute(tail_mma_kernel, cudaFuncAttributeMaxDynamicSharedMemorySize, SMEM_TAIL);

    const double lr_gain = sqrt(2.0 / (1.0 + 0.02 * 0.02));
    const float cw_head = (float)(lr_gain / sqrt(27.0));
    const float cb_head = (float)(1.0 / sqrt(3.0));
    const float cw_body = (float)(lr_gain / 24.0);
    const float cb_body = 0.125f;
    const float cw_tail = (float)((5.0 / 3.0) / 24.0);
    const float cb_tail = 0.125f;

    // weight preps (fold cw, fp16, k-major)
    {
        int N = 5 * 16 * 9 * 64 * 64;
        prep_kernel<<<(N + 255) / 256, 256>>>(body_w, cw_body);
        int M = 16 * 9 * 64 * 8;
        prep_tail_kernel<<<(M + 255) / 256, 256>>>(tail_w, cw_tail);
    }

    // head -> actA (268)
    {
        dim3 grid((268 + 31) / 32, (268 + 7) / 8, BATCH * 4);
        head_kernel<<<grid, 256>>>(noise, head_w, head_b, actA, cw_head, cb_head);
    }

    // 5 body layers, ping-pong
    __half *src = actA, *dst = actB;
    int Sin = 268;
    for (int l = 0; l < 5; l++) {
        dim3 grid(9, 1, BATCH);
        const __half* wt_l = wt + (size_t)l * 16 * 9 * 4096;
        const float* bias_l = body_b + (size_t)l * 16 * 64;
        body_mma_kernel<<<grid, NTHR, SMEM_BODY>>>(src, wt_l, bias_l, dst, Sin, cb_body);
        __half* t = src; src = dst; dst = t;
        Sin -= 2;
    }

    // tail (tensorized): src 258 -> out 256
    {
        dim3 grid(36, 1, BATCH);
        tail_mma_kernel<<<grid, NTHR, SMEM_TAIL>>>(src, tail_b, out, cb_tail);
    }
}